// round 2
// baseline (speedup 1.0000x reference)
#include <cuda_runtime.h>
#include <math.h>

#define B_SZ   1024
#define LATD   64
#define FCON   256
#define IN0    320     // LAT + FCON
#define HIDD   512
#define INTER  576     // LAT + HID
#define NOUT   512
#define NE     8
#define GH     64

// scratch (no allocs allowed)
__device__ float g_coeff[B_SZ * NE];
__device__ float g_out0[B_SZ * HIDD];
__device__ float g_out1[B_SZ * HIDD];

__device__ __forceinline__ float elu_f(float x) {
    return x > 0.0f ? x : expm1f(x);
}

// ---------------- gate: coeff = softmax(elu(elu(x@gw1+gb1)@gw2+gb2)@gw3+gb3) ----------------
__global__ __launch_bounds__(GH) void gate_kernel(
    const float* __restrict__ z, const float* __restrict__ c,
    const float* __restrict__ gw1, const float* __restrict__ gb1,
    const float* __restrict__ gw2, const float* __restrict__ gb2,
    const float* __restrict__ gw3, const float* __restrict__ gb3)
{
    __shared__ float x[IN0];
    __shared__ float h1[GH];
    __shared__ float h2[GH];
    __shared__ float lg[NE];

    int b = blockIdx.x;
    int t = threadIdx.x;  // 64 threads

    x[t] = z[b * LATD + t];
    #pragma unroll
    for (int i = t; i < FCON; i += GH) x[LATD + i] = c[b * FCON + i];
    __syncthreads();

    float acc = gb1[t];
    #pragma unroll 8
    for (int i = 0; i < IN0; i++) acc += x[i] * gw1[i * GH + t];
    h1[t] = elu_f(acc);
    __syncthreads();

    acc = gb2[t];
    #pragma unroll 8
    for (int i = 0; i < GH; i++) acc += h1[i] * gw2[i * GH + t];
    h2[t] = elu_f(acc);
    __syncthreads();

    if (t < NE) {
        float a = gb3[t];
        #pragma unroll 8
        for (int i = 0; i < GH; i++) a += h2[i] * gw3[i * NE + t];
        lg[t] = a;
    }
    __syncthreads();

    if (t < NE) {
        float m = lg[0];
        #pragma unroll
        for (int i = 1; i < NE; i++) m = fmaxf(m, lg[i]);
        float s = 0.0f;
        #pragma unroll
        for (int i = 0; i < NE; i++) s += expf(lg[i] - m);
        g_coeff[b * NE + t] = expf(lg[t] - m) / s;
    }
}

// ---------------- MoE layer as one big SGEMM ----------------
// out[b,o] = act( sum_{e,i} coeff[b,e]*inp[b,i]*w[e,i,o] + sum_e coeff[b,e]*bias[e,o] )
// A'[b, e*IN+i] = coeff[b,e]*inp[b,i] (built on the fly in the A loader)
// W flat [E*IN, 512] is exactly the contiguous layout of w[E, IN, 512].
template<int IN_DIM, bool ACT>
__global__ __launch_bounds__(256)
void moe_kernel(const float* __restrict__ z,
                const float* __restrict__ prev,   // width IN_DIM-LATD (c or previous out)
                const float* __restrict__ w,      // [NE*IN_DIM, NOUT]
                const float* __restrict__ bias,   // [NE, NOUT]
                float* __restrict__ out)          // [B, NOUT]
{
    constexpr int BM = 64, BN = 64, BK = 16, TM = 4, TN = 4;
    constexpr int PREV_W = IN_DIM - LATD;
    constexpr int KTOT = NE * IN_DIM;
    static_assert(IN_DIM % BK == 0, "K-tile must not span an expert boundary");

    __shared__ float As[BK][BM + 4];   // +4 pad: conflict-light stores, 16B-aligned rows
    __shared__ float Bs[BK][BN];

    int tid = threadIdx.x;
    int tx = tid & 15;
    int ty = tid >> 4;
    int m0 = blockIdx.y * BM;
    int n0 = blockIdx.x * BN;

    // A loader: 16 k-positions x 16 m-rows per pass, 4 passes
    int a_k  = tid & (BK - 1);
    int a_m0 = tid >> 4;       // 0..15
    // B loader: 64 n-cols x 4 k-rows per pass, 4 passes
    int b_n  = tid & (BN - 1);
    int b_k0 = tid >> 6;       // 0..3

    float acc[TM][TN] = {};

    for (int k0 = 0; k0 < KTOT; k0 += BK) {
        int e  = k0 / IN_DIM;
        int i0 = k0 - e * IN_DIM;

        // load + scale A tile
        #pragma unroll
        for (int r = 0; r < 4; r++) {
            int m   = a_m0 + r * 16;
            int row = m0 + m;
            int i   = i0 + a_k;
            float v = (i < LATD) ? z[row * LATD + i]
                                 : prev[row * PREV_W + (i - LATD)];
            As[a_k][m] = v * g_coeff[row * NE + e];
        }
        // load B tile (coalesced rows of W)
        #pragma unroll
        for (int r = 0; r < 4; r++) {
            int k = b_k0 + r * 4;
            Bs[k][b_n] = w[(size_t)(k0 + k) * NOUT + n0 + b_n];
        }
        __syncthreads();

        #pragma unroll
        for (int kk = 0; kk < BK; kk++) {
            float a[TM], bb[TN];
            #pragma unroll
            for (int i = 0; i < TM; i++) a[i] = As[kk][ty * TM + i];
            #pragma unroll
            for (int j = 0; j < TN; j++) bb[j] = Bs[kk][tx * TN + j];
            #pragma unroll
            for (int i = 0; i < TM; i++)
                #pragma unroll
                for (int j = 0; j < TN; j++)
                    acc[i][j] += a[i] * bb[j];
        }
        __syncthreads();
    }

    // epilogue: mixed bias + activation
    #pragma unroll
    for (int i = 0; i < TM; i++) {
        int row = m0 + ty * TM + i;
        float cf[NE];
        #pragma unroll
        for (int e = 0; e < NE; e++) cf[e] = g_coeff[row * NE + e];
        #pragma unroll
        for (int j = 0; j < TN; j++) {
            int col = n0 + tx * TN + j;
            float v = acc[i][j];
            #pragma unroll
            for (int e = 0; e < NE; e++) v += cf[e] * bias[e * NOUT + col];
            out[row * NOUT + col] = ACT ? elu_f(v) : v;
        }
    }
}

extern "C" void kernel_launch(void* const* d_in, const int* in_sizes, int n_in,
                              void* d_out, int out_size)
{
    const float* z   = (const float*)d_in[0];
    const float* c   = (const float*)d_in[1];
    const float* w0  = (const float*)d_in[2];
    const float* b0  = (const float*)d_in[3];
    const float* w1  = (const float*)d_in[4];
    const float* b1  = (const float*)d_in[5];
    const float* w2  = (const float*)d_in[6];
    const float* b2  = (const float*)d_in[7];
    const float* gw1 = (const float*)d_in[8];
    const float* gb1 = (const float*)d_in[9];
    const float* gw2 = (const float*)d_in[10];
    const float* gb2 = (const float*)d_in[11];
    const float* gw3 = (const float*)d_in[12];
    const float* gb3 = (const float*)d_in[13];
    float* out = (float*)d_out;

    float* out0;
    float* out1;
    cudaGetSymbolAddress((void**)&out0, g_out0);
    cudaGetSymbolAddress((void**)&out1, g_out1);

    gate_kernel<<<B_SZ, GH>>>(z, c, gw1, gb1, gw2, gb2, gw3, gb3);

    dim3 grid(NOUT / 64, B_SZ / 64);  // (8, 16) = 128 blocks
    moe_kernel<IN0,   true ><<<grid, 256>>>(z, c,    w0, b0, out0);
    moe_kernel<INTER, true ><<<grid, 256>>>(z, out0, w1, b1, out1);
    moe_kernel<INTER, false><<<grid, 256>>>(z, out1, w2, b2, out);
}

// round 4
// speedup vs baseline: 3.2801x; 3.2801x over previous
#include <cuda_runtime.h>
#include <cuda_bf16.h>
#include <math.h>
#include <stdint.h>

#define B_SZ 1024
#define LATD 64
#define FCON 256
#define IN0  320
#define HIDD 512
#define INTER 576
#define NOUT 512
#define NE   8
#define GH   64
#define K0P  2624   // 8*320+64 (bias tail)
#define K1P  4672   // 8*576+64

__device__ float g_coeff[B_SZ*NE];
__device__ float g_out0[B_SZ*HIDD];
__device__ float g_out1[B_SZ*HIDD];
__device__ __nv_bfloat16 g_Ahi[B_SZ*K1P];
__device__ __nv_bfloat16 g_Alo[B_SZ*K1P];
__device__ __nv_bfloat16 g_Whi[NOUT*K1P];
__device__ __nv_bfloat16 g_Wlo[NOUT*K1P];

__device__ __forceinline__ float elu_f(float x){ return x > 0.0f ? x : expm1f(x); }

__device__ __forceinline__ uint32_t smem_u32(const void* p){
    uint32_t a;
    asm("{ .reg .u64 t; cvta.to.shared.u64 t, %1; cvt.u32.u64 %0, t; }" : "=r"(a) : "l"(p));
    return a;
}

#define CP16(s, g) asm volatile("cp.async.cg.shared.global [%0], [%1], 16;" :: "r"(s), "l"(g))
#define CP_COMMIT() asm volatile("cp.async.commit_group;" ::: "memory")
#define CP_WAIT1()  asm volatile("cp.async.wait_group 1;" ::: "memory")
#define CP_WAIT0()  asm volatile("cp.async.wait_group 0;" ::: "memory")

#define LDSM4(r0,r1,r2,r3,addr) \
    asm volatile("ldmatrix.sync.aligned.m8n8.x4.shared.b16 {%0,%1,%2,%3}, [%4];" \
        : "=r"(r0), "=r"(r1), "=r"(r2), "=r"(r3) : "r"(addr))

#define MMA16816(c, a0,a1,a2,a3, b0,b1) \
    asm volatile("mma.sync.aligned.m16n8k16.row.col.f32.bf16.bf16.f32 " \
        "{%0,%1,%2,%3}, {%4,%5,%6,%7}, {%8,%9}, {%0,%1,%2,%3};" \
        : "+f"((c)[0]), "+f"((c)[1]), "+f"((c)[2]), "+f"((c)[3]) \
        : "r"(a0), "r"(a1), "r"(a2), "r"(a3), "r"(b0), "r"(b1))

__device__ __forceinline__ void split_pair(float a, float b, uint32_t& h, uint32_t& l){
    __nv_bfloat16 ha = __float2bfloat16_rn(a), hb = __float2bfloat16_rn(b);
    __nv_bfloat16 la = __float2bfloat16_rn(a - __bfloat162float(ha));
    __nv_bfloat16 lb = __float2bfloat16_rn(b - __bfloat162float(hb));
    __nv_bfloat162 H = __halves2bfloat162(ha, hb), L = __halves2bfloat162(la, lb);
    h = *reinterpret_cast<uint32_t*>(&H); l = *reinterpret_cast<uint32_t*>(&L);
}

// ---------------- gate ----------------
__global__ __launch_bounds__(GH) void gate_kernel(
    const float* __restrict__ z, const float* __restrict__ c,
    const float* __restrict__ gw1, const float* __restrict__ gb1,
    const float* __restrict__ gw2, const float* __restrict__ gb2,
    const float* __restrict__ gw3, const float* __restrict__ gb3)
{
    __shared__ float x[IN0], h1[GH], h2[GH], lg[NE];
    int b = blockIdx.x, t = threadIdx.x;
    x[t] = z[b*LATD + t];
    for (int i = t; i < FCON; i += GH) x[LATD+i] = c[b*FCON + i];
    __syncthreads();
    float acc = gb1[t];
    #pragma unroll 8
    for (int i = 0; i < IN0; i++) acc += x[i]*gw1[i*GH + t];
    h1[t] = elu_f(acc);
    __syncthreads();
    acc = gb2[t];
    #pragma unroll 8
    for (int i = 0; i < GH; i++) acc += h1[i]*gw2[i*GH + t];
    h2[t] = elu_f(acc);
    __syncthreads();
    if (t < NE){
        float a = gb3[t];
        #pragma unroll 8
        for (int i = 0; i < GH; i++) a += h2[i]*gw3[i*NE + t];
        lg[t] = a;
    }
    __syncthreads();
    if (t < NE){
        float m = lg[0];
        #pragma unroll
        for (int i = 1; i < NE; i++) m = fmaxf(m, lg[i]);
        float s = 0.f;
        #pragma unroll
        for (int i = 0; i < NE; i++) s += expf(lg[i]-m);
        g_coeff[b*NE + t] = expf(lg[t]-m)/s;
    }
}

// ---------------- W transpose: fp32 [KTOT,512] -> bf16 hi/lo [512,KP] ----------------
__global__ void transpose_kernel(const float* __restrict__ W, int KP,
                                 __nv_bfloat16* __restrict__ Whi, __nv_bfloat16* __restrict__ Wlo)
{
    __shared__ float tile[32][33];
    int k0 = blockIdx.x*32, n0 = blockIdx.y*32;
    int x = threadIdx.x, y = threadIdx.y;
    #pragma unroll
    for (int j = 0; j < 32; j += 8)
        tile[y+j][x] = W[(size_t)(k0+y+j)*NOUT + n0 + x];
    __syncthreads();
    #pragma unroll
    for (int j = 0; j < 32; j += 8){
        float v = tile[x][y+j];
        int n = n0+y+j, k = k0+x;
        __nv_bfloat16 h = __float2bfloat16_rn(v);
        __nv_bfloat16 l = __float2bfloat16_rn(v - __bfloat162float(h));
        Whi[(size_t)n*KP + k] = h; Wlo[(size_t)n*KP + k] = l;
    }
}
__global__ void tail_kernel(const float* __restrict__ bias, int KTOT, int KP,
                            __nv_bfloat16* __restrict__ Whi, __nv_bfloat16* __restrict__ Wlo)
{
    int t = blockIdx.x*256 + threadIdx.x;
    if (t >= NOUT*64) return;
    int n = t >> 6, j = t & 63;
    float v = (j < NE) ? bias[j*NOUT + n] : 0.0f;
    __nv_bfloat16 h = __float2bfloat16_rn(v);
    __nv_bfloat16 l = __float2bfloat16_rn(v - __bfloat162float(h));
    Whi[(size_t)n*KP + KTOT + j] = h; Wlo[(size_t)n*KP + KTOT + j] = l;
}

// ---------------- A' build ----------------
__global__ __launch_bounds__(256) void prep_kernel(
    const float* __restrict__ z, const float* __restrict__ prev,
    int prev_w, int IN, int KP,
    __nv_bfloat16* __restrict__ Ahi, __nv_bfloat16* __restrict__ Alo)
{
    int b = blockIdx.x, tid = threadIdx.x;
    __shared__ float cf[NE];
    if (tid < NE) cf[tid] = g_coeff[b*NE + tid];
    __syncthreads();
    const float4* z4 = (const float4*)(z + (size_t)b*LATD);
    const float4* p4 = (const float4*)(prev + (size_t)b*prev_w);
    uint4* oh = (uint4*)(Ahi + (size_t)b*KP);
    uint4* ol = (uint4*)(Alo + (size_t)b*KP);
    int inu = IN >> 3, main_u = NE*inu, NU = KP >> 3;
    for (int u = tid; u < NU; u += 256){
        float v[8];
        if (u < main_u){
            int e = u/inu, i8 = (u - e*inu) << 3;
            float s = cf[e];
            float4 x0, x1;
            if (i8 < LATD){ x0 = z4[i8>>2]; x1 = z4[(i8>>2)+1]; }
            else { int q = (i8-LATD)>>2; x0 = p4[q]; x1 = p4[q+1]; }
            v[0]=x0.x*s; v[1]=x0.y*s; v[2]=x0.z*s; v[3]=x0.w*s;
            v[4]=x1.x*s; v[5]=x1.y*s; v[6]=x1.z*s; v[7]=x1.w*s;
        } else {
            int j = (u - main_u) << 3;
            #pragma unroll
            for (int l = 0; l < 8; l++) v[l] = (j+l < NE) ? cf[j+l] : 0.0f;
        }
        uint4 hh, ll;
        split_pair(v[0],v[1],hh.x,ll.x); split_pair(v[2],v[3],hh.y,ll.y);
        split_pair(v[4],v[5],hh.z,ll.z); split_pair(v[6],v[7],hh.w,ll.w);
        oh[u] = hh; ol[u] = ll;
    }
}

// ---------------- mma.sync GEMM: out[1024,512] = A'[1024,KP] @ Wt[512,KP]^T ----------------
// CTA tile 64x64, BK=64, double-buffered cp.async, 8 warps (2 m x 4 n), warp tile 32x16.
// Stage layout (32KB): AH@0 AL@8192 BH@16384 BL@24576; stage stride 32768.
#define GSMEM 65536

template<int KT, bool ACT>
__global__ __launch_bounds__(256) void gemm_kernel(
    const __nv_bfloat16* __restrict__ Ahi, const __nv_bfloat16* __restrict__ Alo,
    const __nv_bfloat16* __restrict__ Whi, const __nv_bfloat16* __restrict__ Wlo,
    float* __restrict__ out)
{
    constexpr int KP = KT*64;
    extern __shared__ char smem[];
    const uint32_t sb = smem_u32(smem);
    const int tid = threadIdx.x, wid = tid >> 5, L = tid & 31;
    const int m0 = blockIdx.y*64, n0 = blockIdx.x*64;
    const int wm = (wid & 1)*32, wn = (wid >> 1)*16;

    // cp.async per-thread offsets (2 chunks each for A and B tiles; same for hi/lo)
    uint32_t s_a[2], s_b[2];
    const __nv_bfloat16 *gah[2], *gal[2], *gbh[2], *gbl[2];
    #pragma unroll
    for (int r = 0; r < 2; r++){
        int ch = tid + r*256, row = ch >> 3, kc = ch & 7;
        uint32_t so = row*128 + ((kc*16) ^ ((row & 7) << 4));
        s_a[r] = so; s_b[r] = so;
        gah[r] = Ahi + (size_t)(m0+row)*KP + kc*8;
        gal[r] = Alo + (size_t)(m0+row)*KP + kc*8;
        gbh[r] = Whi + (size_t)(n0+row)*KP + kc*8;
        gbl[r] = Wlo + (size_t)(n0+row)*KP + kc*8;
    }

    // ldmatrix lane address components
    const int alf = (L & 7) + ((L >> 3) & 1)*8;   // A fragment row 0..15
    const int acb = (L >> 4)*16;                  // A col byte (0|16)
    const int axor = (alf & 7) << 4;
    const uint32_t arow0 = (uint32_t)(wm + alf)*128;
    const uint32_t arow1 = (uint32_t)(wm + 16 + alf)*128;
    const int blf = (L & 7) + (L >> 4)*8;         // B fragment row 0..15
    const int bcb = ((L >> 3) & 1)*16;
    const int bxor = (blf & 7) << 4;
    const uint32_t brow = (uint32_t)(wn + blf)*128;

    float acc[2][2][4];
    #pragma unroll
    for (int i = 0; i < 2; i++)
        #pragma unroll
        for (int j = 0; j < 2; j++)
            #pragma unroll
            for (int q = 0; q < 4; q++) acc[i][j][q] = 0.0f;

    // prologue
    {
        uint32_t st = sb;
        #pragma unroll
        for (int r = 0; r < 2; r++){
            CP16(st +         s_a[r], gah[r]);
            CP16(st + 8192  + s_a[r], gal[r]);
            CP16(st + 16384 + s_b[r], gbh[r]);
            CP16(st + 24576 + s_b[r], gbl[r]);
        }
        CP_COMMIT();
    }

    for (int t = 0; t < KT; t++){
        if (t + 1 < KT){
            uint32_t st = sb + ((t+1) & 1)*32768;
            size_t kb = (size_t)(t+1)*64;
            #pragma unroll
            for (int r = 0; r < 2; r++){
                CP16(st +         s_a[r], gah[r] + kb);
                CP16(st + 8192  + s_a[r], gal[r] + kb);
                CP16(st + 16384 + s_b[r], gbh[r] + kb);
                CP16(st + 24576 + s_b[r], gbl[r] + kb);
            }
            CP_COMMIT();
            CP_WAIT1();
        } else {
            CP_WAIT0();
        }
        __syncthreads();

        const uint32_t st = sb + (t & 1)*32768;
        #pragma unroll
        for (int ks = 0; ks < 4; ks++){
            const uint32_t ca = (uint32_t)((ks*32 + acb) ^ axor);
            const uint32_t cb = (uint32_t)((ks*32 + bcb) ^ bxor);
            uint32_t ah0[4], ah1[4], al0[4], al1[4], bh[4], bl[4];
            LDSM4(ah0[0],ah0[1],ah0[2],ah0[3], st + arow0 + ca);
            LDSM4(ah1[0],ah1[1],ah1[2],ah1[3], st + arow1 + ca);
            LDSM4(al0[0],al0[1],al0[2],al0[3], st + 8192 + arow0 + ca);
            LDSM4(al1[0],al1[1],al1[2],al1[3], st + 8192 + arow1 + ca);
            LDSM4(bh[0],bh[1],bh[2],bh[3],     st + 16384 + brow + cb);
            LDSM4(bl[0],bl[1],bl[2],bl[3],     st + 24576 + brow + cb);

            MMA16816(acc[0][0], ah0[0],ah0[1],ah0[2],ah0[3], bh[0],bh[1]);
            MMA16816(acc[0][1], ah0[0],ah0[1],ah0[2],ah0[3], bh[2],bh[3]);
            MMA16816(acc[1][0], ah1[0],ah1[1],ah1[2],ah1[3], bh[0],bh[1]);
            MMA16816(acc[1][1], ah1[0],ah1[1],ah1[2],ah1[3], bh[2],bh[3]);
            MMA16816(acc[0][0], al0[0],al0[1],al0[2],al0[3], bh[0],bh[1]);
            MMA16816(acc[0][1], al0[0],al0[1],al0[2],al0[3], bh[2],bh[3]);
            MMA16816(acc[1][0], al1[0],al1[1],al1[2],al1[3], bh[0],bh[1]);
            MMA16816(acc[1][1], al1[0],al1[1],al1[2],al1[3], bh[2],bh[3]);
            MMA16816(acc[0][0], ah0[0],ah0[1],ah0[2],ah0[3], bl[0],bl[1]);
            MMA16816(acc[0][1], ah0[0],ah0[1],ah0[2],ah0[3], bl[2],bl[3]);
            MMA16816(acc[1][0], ah1[0],ah1[1],ah1[2],ah1[3], bl[0],bl[1]);
            MMA16816(acc[1][1], ah1[0],ah1[1],ah1[2],ah1[3], bl[2],bl[3]);
        }
        __syncthreads();
    }

    // epilogue
    const int g = L >> 2, tg = L & 3;
    #pragma unroll
    for (int i = 0; i < 2; i++){
        #pragma unroll
        for (int j = 0; j < 2; j++){
            int row = m0 + wm + i*16 + g;
            int col = n0 + wn + j*8 + 2*tg;
            float2 v0, v1;
            v0.x = ACT ? elu_f(acc[i][j][0]) : acc[i][j][0];
            v0.y = ACT ? elu_f(acc[i][j][1]) : acc[i][j][1];
            v1.x = ACT ? elu_f(acc[i][j][2]) : acc[i][j][2];
            v1.y = ACT ? elu_f(acc[i][j][3]) : acc[i][j][3];
            *(float2*)(out + (size_t)row*NOUT + col) = v0;
            *(float2*)(out + (size_t)(row+8)*NOUT + col) = v1;
        }
    }
}

extern "C" void kernel_launch(void* const* d_in, const int* in_sizes, int n_in,
                              void* d_out, int out_size)
{
    const float* z   = (const float*)d_in[0];
    const float* c   = (const float*)d_in[1];
    const float* w0  = (const float*)d_in[2];
    const float* b0  = (const float*)d_in[3];
    const float* w1  = (const float*)d_in[4];
    const float* b1  = (const float*)d_in[5];
    const float* w2  = (const float*)d_in[6];
    const float* b2  = (const float*)d_in[7];
    const float* gw1 = (const float*)d_in[8];
    const float* gb1 = (const float*)d_in[9];
    const float* gw2 = (const float*)d_in[10];
    const float* gb2 = (const float*)d_in[11];
    const float* gw3 = (const float*)d_in[12];
    const float* gb3 = (const float*)d_in[13];
    float* out = (float*)d_out;

    float *out0, *out1;
    __nv_bfloat16 *Ahi, *Alo, *Whi, *Wlo;
    cudaGetSymbolAddress((void**)&out0, g_out0);
    cudaGetSymbolAddress((void**)&out1, g_out1);
    cudaGetSymbolAddress((void**)&Ahi, g_Ahi);
    cudaGetSymbolAddress((void**)&Alo, g_Alo);
    cudaGetSymbolAddress((void**)&Whi, g_Whi);
    cudaGetSymbolAddress((void**)&Wlo, g_Wlo);

    cudaFuncSetAttribute(gemm_kernel<K0P/64, true>,  cudaFuncAttributeMaxDynamicSharedMemorySize, GSMEM);
    cudaFuncSetAttribute(gemm_kernel<K1P/64, true>,  cudaFuncAttributeMaxDynamicSharedMemorySize, GSMEM);
    cudaFuncSetAttribute(gemm_kernel<K1P/64, false>, cudaFuncAttributeMaxDynamicSharedMemorySize, GSMEM);

    dim3 tb(32, 8);
    dim3 gg(8, 16);   // 128 CTAs

    gate_kernel<<<B_SZ, GH>>>(z, c, gw1, gb1, gw2, gb2, gw3, gb3);

    // layer 0
    transpose_kernel<<<dim3((NE*IN0)/32, 16), tb>>>(w0, K0P, Whi, Wlo);
    tail_kernel<<<NOUT*64/256, 256>>>(b0, NE*IN0, K0P, Whi, Wlo);
    prep_kernel<<<B_SZ, 256>>>(z, c, FCON, IN0, K0P, Ahi, Alo);
    gemm_kernel<K0P/64, true><<<gg, 256, GSMEM>>>(Ahi, Alo, Whi, Wlo, out0);

    // layer 1
    transpose_kernel<<<dim3((NE*INTER)/32, 16), tb>>>(w1, K1P, Whi, Wlo);
    tail_kernel<<<NOUT*64/256, 256>>>(b1, NE*INTER, K1P, Whi, Wlo);
    prep_kernel<<<B_SZ, 256>>>(z, out0, HIDD, INTER, K1P, Ahi, Alo);
    gemm_kernel<K1P/64, true><<<gg, 256, GSMEM>>>(Ahi, Alo, Whi, Wlo, out1);

    // layer 2
    transpose_kernel<<<dim3((NE*INTER)/32, 16), tb>>>(w2, K1P, Whi, Wlo);
    tail_kernel<<<NOUT*64/256, 256>>>(b2, NE*INTER, K1P, Whi, Wlo);
    prep_kernel<<<B_SZ, 256>>>(z, out1, HIDD, INTER, K1P, Ahi, Alo);
    gemm_kernel<K1P/64, false><<<gg, 256, GSMEM>>>(Ahi, Alo, Whi, Wlo, out);
}